// round 12
// baseline (speedup 1.0000x reference)
#include <cuda_runtime.h>
#include <cuda_bf16.h>
#include <math.h>
#include <stdint.h>

#define BB 32
#define SS 8192
#define DD 256
#define HH 256

// device-global scratch (allocation-free rule)
__device__ float g_inp[BB * HH];
__device__ __nv_bfloat16 g_Bh[HH * DD];      // W_ctx hi (bf16), [h][d]
__device__ __nv_bfloat16 g_Bl[HH * DD];      // W_ctx lo
__device__ float g_att[BB * SS];             // raw tanh-dot sums (pre 10*tanh)

// ---------------------------------------------------------------------------
__device__ __forceinline__ uint32_t smem_u32(const void* p) {
    uint32_t a;
    asm("{ .reg .u64 t; cvta.to.shared.u64 t, %1; cvt.u32.u64 %0, t; }" : "=r"(a) : "l"(p));
    return a;
}
#define CP_ASYNC16(dst, src) \
    asm volatile("cp.async.cg.shared.global [%0], [%1], 16;" :: "r"(dst), "l"(src))
#define CP_COMMIT() asm volatile("cp.async.commit_group;" ::: "memory")
#define CP_WAIT0()  asm volatile("cp.async.wait_group 0;" ::: "memory")

#define BAR_SYNC(id, cnt)   asm volatile("bar.sync %0, %1;"   :: "r"(id), "r"(cnt) : "memory")
#define BAR_ARRIVE(id, cnt) asm volatile("bar.arrive %0, %1;" :: "r"(id), "r"(cnt) : "memory")

#define LDSM4(r0, r1, r2, r3, a) \
    asm volatile("ldmatrix.sync.aligned.m8n8.x4.shared.b16 {%0,%1,%2,%3}, [%4];" \
        : "=r"(r0), "=r"(r1), "=r"(r2), "=r"(r3) : "r"(a))

#define MMA_BF16(c, A, b0, b1) \
    asm volatile("mma.sync.aligned.m16n8k16.row.col.f32.bf16.bf16.f32 " \
        "{%0,%1,%2,%3},{%4,%5,%6,%7},{%8,%9},{%0,%1,%2,%3};" \
        : "+f"((c)[0]), "+f"((c)[1]), "+f"((c)[2]), "+f"((c)[3]) \
        : "r"((A)[0]), "r"((A)[1]), "r"((A)[2]), "r"((A)[3]), "r"(b0), "r"(b1))

// ---------------------------------------------------------------------------
// Kernel 1: inp[b,h] = b_in[h] + sum_d x[b,d] * W_in[h,d]
// ---------------------------------------------------------------------------
__global__ void k_inp(const float* __restrict__ x, const float* __restrict__ W_in,
                      const float* __restrict__ b_in) {
    int b = blockIdx.x, h = threadIdx.x;
    __shared__ float xs[HH];
    xs[h] = x[b * HH + h];
    __syncthreads();
    float acc = b_in[h];
    const float* w = W_in + h * HH;
#pragma unroll 8
    for (int d0 = 0; d0 < HH; d0 += 4) {
        float4 w4 = *(const float4*)(w + d0);
        acc += xs[d0] * w4.x + xs[d0+1] * w4.y + xs[d0+2] * w4.z + xs[d0+3] * w4.w;
    }
    g_inp[b * HH + h] = acc;
}

// ---------------------------------------------------------------------------
// Kernel 2: split W_ctx fp32 -> bf16 hi/lo
// ---------------------------------------------------------------------------
__global__ void k_wsplit(const float* __restrict__ W) {
    int i = blockIdx.x * 256 + threadIdx.x;
    float v = W[i];
    __nv_bfloat16 h = __float2bfloat16_rn(v);
    g_Bh[i] = h;
    g_Bl[i] = __float2bfloat16_rn(v - __bfloat162float(h));
}

// ---------------------------------------------------------------------------
// Kernel 3: zero g_att (atomic combine target; re-zeroed every graph replay)
// ---------------------------------------------------------------------------
__global__ void k_zero() {
    int i = blockIdx.x * blockDim.x + threadIdx.x;
    ((float4*)g_att)[i] = make_float4(0.f, 0.f, 0.f, 0.f);
}

// ---------------------------------------------------------------------------
// Kernel 4: warp-specialized split-bf16 HMMA GEMM, N split across 2 CTAs.
// CTA = 384 threads: warps 0-7 consumers (pure LDSM+MMA), warps 8-11
// producers (cp.async B, LDG+convert+STS A). 3-stage ring, named barriers:
//   full[s] = id 1+s, free[s] = id 4+s, all count 384.
// Consumer tile: M=64 x N=128 (its n-half), warp 32x32, K=256 in 8 x 32.
// acc = Ah*Bh + Ah*Bl + Al*Bh  (lo*lo dropped ~2^-18)
// ---------------------------------------------------------------------------
#define MT 64
#define KT 32
#define NT (DD / KT)
#define PITCH 80
#define STG 30720          // stage stride: Ah 5120 | Al 5120 | Bh 10240 | Bl 10240
#define OFF_IB  92160
#define OFF_V   93184
#define OFF_P   94208
#define SMEM_TOTAL 95232

__global__ __launch_bounds__(384, 2) void k_main(const float* __restrict__ context,
                                                 const float* __restrict__ b_ctx,
                                                 const float* __restrict__ V) {
    extern __shared__ char smem[];
    uint32_t sb = smem_u32(smem);
    int tid = threadIdx.x;
    int wid = tid >> 5, lid = tid & 31;
    int b = blockIdx.y;
    int m0 = blockIdx.x * MT;
    int hb = blockIdx.z * 128;

    const float* ctx = context + ((long)b * SS + m0) * DD;

    if (wid < 8) {
        // =============== CONSUMERS: warps 0-7 ===============
        int wm = wid & 1, wn = wid >> 1;
        float* ibs = (float*)(smem + OFF_IB);
        float* vvs = (float*)(smem + OFF_V);
        ibs[tid] = g_inp[b * HH + tid] + b_ctx[tid];   // tid < 256 here
        vvs[tid] = V[tid];

        float c[2][4][4];
#pragma unroll
        for (int mi = 0; mi < 2; mi++)
#pragma unroll
            for (int j = 0; j < 4; j++)
#pragma unroll
                for (int e = 0; e < 4; e++) c[mi][j][e] = 0.f;

#pragma unroll 1
        for (int kt = 0; kt < NT; kt++) {
            int s = kt % 3;
            BAR_SYNC(1 + s, 384);                       // wait stage full
            uint32_t abase = sb + s * STG;
            uint32_t bbase = sb + s * STG + 10240;
#pragma unroll
            for (int ks = 0; ks < 2; ks++) {
                uint32_t aH[2][4], aL[2][4], bH[2][4], bL[2][4];
                int arow_f = wm * 32 + (lid & 15);
                int acol_b = ks * 32 + (lid >> 4) * 16;
#pragma unroll
                for (int mi = 0; mi < 2; mi++) {
                    uint32_t ad = abase + (arow_f + mi * 16) * PITCH + acol_b;
                    LDSM4(aH[mi][0], aH[mi][1], aH[mi][2], aH[mi][3], ad);
                    LDSM4(aL[mi][0], aL[mi][1], aL[mi][2], aL[mi][3], ad + 5120);
                }
                int brow_f = wn * 32 + (lid & 7) + ((lid >> 4) * 8);
                int bcol_b = ks * 32 + ((lid >> 3) & 1) * 16;
#pragma unroll
                for (int jp = 0; jp < 2; jp++) {
                    uint32_t bd = bbase + (brow_f + jp * 16) * PITCH + bcol_b;
                    LDSM4(bH[jp][0], bH[jp][1], bH[jp][2], bH[jp][3], bd);
                    LDSM4(bL[jp][0], bL[jp][1], bL[jp][2], bL[jp][3], bd + 10240);
                }
#pragma unroll
                for (int mi = 0; mi < 2; mi++)
#pragma unroll
                    for (int j = 0; j < 4; j++) {
                        uint32_t h0 = bH[j >> 1][(j & 1) * 2], h1 = bH[j >> 1][(j & 1) * 2 + 1];
                        uint32_t l0 = bL[j >> 1][(j & 1) * 2], l1 = bL[j >> 1][(j & 1) * 2 + 1];
                        MMA_BF16(c[mi][j], aH[mi], h0, h1);
                        MMA_BF16(c[mi][j], aH[mi], l0, l1);
                        MMA_BF16(c[mi][j], aL[mi], h0, h1);
                    }
            }
            BAR_ARRIVE(4 + s, 384);                     // release stage
        }

        // ---- epilogue: partial tanh-dot over this CTA's 128 h ----
        int q = lid & 3, g = lid >> 2;
        float ps[2][2] = {{0.f, 0.f}, {0.f, 0.f}};
#pragma unroll
        for (int mi = 0; mi < 2; mi++)
#pragma unroll
            for (int j = 0; j < 4; j++) {
                int h0 = hb + wn * 32 + j * 8 + q * 2;
                ps[mi][0] += vvs[h0]   * tanhf(c[mi][j][0] + ibs[h0]);
                ps[mi][0] += vvs[h0+1] * tanhf(c[mi][j][1] + ibs[h0+1]);
                ps[mi][1] += vvs[h0]   * tanhf(c[mi][j][2] + ibs[h0]);
                ps[mi][1] += vvs[h0+1] * tanhf(c[mi][j][3] + ibs[h0+1]);
            }
#pragma unroll
        for (int off = 1; off <= 2; off <<= 1) {
#pragma unroll
            for (int mi = 0; mi < 2; mi++) {
                ps[mi][0] += __shfl_xor_sync(0xffffffffu, ps[mi][0], off);
                ps[mi][1] += __shfl_xor_sync(0xffffffffu, ps[mi][1], off);
            }
        }
        float* part = (float*)(smem + OFF_P);
        if (q == 0) {
#pragma unroll
            for (int mi = 0; mi < 2; mi++) {
                part[(wm * 32 + mi * 16 + g) * 4 + wn]     = ps[mi][0];
                part[(wm * 32 + mi * 16 + g + 8) * 4 + wn] = ps[mi][1];
            }
        }
        BAR_SYNC(7, 256);                               // consumers only
        if (tid < MT) {
            float ssum = part[tid * 4] + part[tid * 4 + 1] + part[tid * 4 + 2] + part[tid * 4 + 3];
            atomicAdd(&g_att[b * SS + m0 + tid], ssum);
        }
    } else {
        // =============== PRODUCERS: warps 8-11 (128 threads) ===============
        int ptid = tid - 256;
#pragma unroll 1
        for (int kt = 0; kt < NT; kt++) {
            int s = kt % 3;
            int k0 = kt * KT;
            if (kt >= 3) BAR_SYNC(4 + s, 384);          // wait stage free
            uint32_t stage = sb + s * STG;
            // ---- B via cp.async: 1024 16B chunks, 8 per thread
#pragma unroll
            for (int r = 0; r < 8; r++) {
                int idx = ptid + 128 * r;
                int mat = idx >> 9, rem = idx & 511;
                int row = rem >> 2, cc = rem & 3;
                const __nv_bfloat16* src = (mat ? g_Bl : g_Bh) + (hb + row) * DD + k0 + cc * 8;
                CP_ASYNC16(stage + 10240 + mat * 10240 + row * PITCH + cc * 16, src);
            }
            CP_COMMIT();
            // ---- A: LDG fp32, split hi/lo, STS (overlaps B flight)
#pragma unroll
            for (int r = 0; r < 4; r++) {
                int f = ptid + 128 * r;
                int row = f >> 3, seg = f & 7;
                float4 v4 = *(const float4*)(ctx + row * DD + k0 + seg * 4);
                __nv_bfloat16 h0 = __float2bfloat16_rn(v4.x), h1 = __float2bfloat16_rn(v4.y);
                __nv_bfloat16 h2 = __float2bfloat16_rn(v4.z), h3 = __float2bfloat16_rn(v4.w);
                __nv_bfloat16 l0 = __float2bfloat16_rn(v4.x - __bfloat162float(h0));
                __nv_bfloat16 l1 = __float2bfloat16_rn(v4.y - __bfloat162float(h1));
                __nv_bfloat16 l2 = __float2bfloat16_rn(v4.z - __bfloat162float(h2));
                __nv_bfloat16 l3 = __float2bfloat16_rn(v4.w - __bfloat162float(h3));
                uint2 ph = make_uint2(
                    (uint32_t)__bfloat16_as_ushort(h0) | ((uint32_t)__bfloat16_as_ushort(h1) << 16),
                    (uint32_t)__bfloat16_as_ushort(h2) | ((uint32_t)__bfloat16_as_ushort(h3) << 16));
                uint2 pl = make_uint2(
                    (uint32_t)__bfloat16_as_ushort(l0) | ((uint32_t)__bfloat16_as_ushort(l1) << 16),
                    (uint32_t)__bfloat16_as_ushort(l2) | ((uint32_t)__bfloat16_as_ushort(l3) << 16));
                char* base = smem + s * STG + row * PITCH + seg * 8;
                *(uint2*)(base)        = ph;
                *(uint2*)(base + 5120) = pl;
            }
            CP_WAIT0();                                 // B landed
            BAR_ARRIVE(1 + s, 384);                     // publish stage
        }
    }
}

// ---------------------------------------------------------------------------
// Kernel 5: mask echo + masked argmax + p = exp(max)/sum(exp).
// g_att holds raw sums; att = 10*tanh(v) in [-10,10], exp can't overflow.
// ---------------------------------------------------------------------------
__global__ __launch_bounds__(1024) void k_reduce(const int* __restrict__ mask,
                                                 float* __restrict__ out) {
    int b = blockIdx.x, tid = threadIdx.x;
    __shared__ float smax[1024], ssum[1024];
    __shared__ int   sidx[1024];

    float best = -INFINITY, se = 0.f;
    int bidx = 0x7fffffff;
    for (int s = tid; s < SS; s += 1024) {
        int m = mask[b * SS + s];
        out[2 * BB + b * SS + s] = m ? 1.f : 0.f;
        if (m) {
            float v = 10.f * tanhf(g_att[b * SS + s]);
            se += expf(v);
            if (v > best || (v == best && s < bidx)) { best = v; bidx = s; }
        }
    }
    smax[tid] = best; sidx[tid] = bidx; ssum[tid] = se;
    __syncthreads();
    for (int off = 512; off; off >>= 1) {
        if (tid < off) {
            float v = smax[tid + off]; int ix = sidx[tid + off];
            if (v > smax[tid] || (v == smax[tid] && ix < sidx[tid])) {
                smax[tid] = v; sidx[tid] = ix;
            }
            ssum[tid] += ssum[tid + off];
        }
        __syncthreads();
    }
    if (tid == 0) {
        float rowmax = smax[0];
        out[b]      = (float)((rowmax == -INFINITY) ? 0 : sidx[0]);
        out[BB + b] = expf(rowmax) / ssum[0];
    }
}

// ---------------------------------------------------------------------------
extern "C" void kernel_launch(void* const* d_in, const int* in_sizes, int n_in,
                              void* d_out, int out_size) {
    const float* x      = (const float*)d_in[0];
    const float* contex = (const float*)d_in[1];
    const int*   mask   = (const int*)  d_in[2];
    const float* W_in   = (const float*)d_in[3];
    const float* b_in   = (const float*)d_in[4];
    const float* W_ctx  = (const float*)d_in[5];
    const float* b_ctx  = (const float*)d_in[6];
    const float* V      = (const float*)d_in[7];
    float* out = (float*)d_out;

    cudaFuncSetAttribute(k_main, cudaFuncAttributeMaxDynamicSharedMemorySize, SMEM_TOTAL);

    k_inp<<<BB, HH>>>(x, W_in, b_in);
    k_wsplit<<<HH * DD / 256, 256>>>(W_ctx);
    k_zero<<<BB * SS / 4 / 256, 256>>>();
    k_main<<<dim3(SS / MT, BB, 2), 384, SMEM_TOTAL>>>(contex, b_ctx, V);
    k_reduce<<<BB, 1024>>>(mask, out);
}

// round 13
// speedup vs baseline: 1.0750x; 1.0750x over previous
#include <cuda_runtime.h>
#include <cuda_bf16.h>
#include <math.h>
#include <stdint.h>

#define BB 32
#define SS 8192
#define DD 256
#define HH 256

// device-global scratch (allocation-free rule)
__device__ float g_inp[BB * HH];
__device__ __nv_bfloat16 g_Bh[HH * DD];      // W_ctx hi (bf16), [h][d]
__device__ __nv_bfloat16 g_Bl[HH * DD];      // W_ctx lo
__device__ float g_att[BB * SS];             // logits post 10*tanh

// ---------------------------------------------------------------------------
__device__ __forceinline__ uint32_t smem_u32(const void* p) {
    uint32_t a;
    asm("{ .reg .u64 t; cvta.to.shared.u64 t, %1; cvt.u32.u64 %0, t; }" : "=r"(a) : "l"(p));
    return a;
}
#define CP_ASYNC16(dst, src) \
    asm volatile("cp.async.cg.shared.global [%0], [%1], 16;" :: "r"(dst), "l"(src))
#define CP_COMMIT() asm volatile("cp.async.commit_group;" ::: "memory")
#define CP_WAIT0()  asm volatile("cp.async.wait_group 0;" ::: "memory")

#define LDSM4(r0, r1, r2, r3, a) \
    asm volatile("ldmatrix.sync.aligned.m8n8.x4.shared.b16 {%0,%1,%2,%3}, [%4];" \
        : "=r"(r0), "=r"(r1), "=r"(r2), "=r"(r3) : "r"(a))

#define MMA_BF16(c, A, b0, b1) \
    asm volatile("mma.sync.aligned.m16n8k16.row.col.f32.bf16.bf16.f32 " \
        "{%0,%1,%2,%3},{%4,%5,%6,%7},{%8,%9},{%0,%1,%2,%3};" \
        : "+f"((c)[0]), "+f"((c)[1]), "+f"((c)[2]), "+f"((c)[3]) \
        : "r"((A)[0]), "r"((A)[1]), "r"((A)[2]), "r"((A)[3]), "r"(b0), "r"(b1))

// ---------------------------------------------------------------------------
// Kernel 1: inp[b,h] = b_in[h] + sum_d x[b,d] * W_in[h,d]
// ---------------------------------------------------------------------------
__global__ void k_inp(const float* __restrict__ x, const float* __restrict__ W_in,
                      const float* __restrict__ b_in) {
    int b = blockIdx.x, h = threadIdx.x;
    __shared__ float xs[HH];
    xs[h] = x[b * HH + h];
    __syncthreads();
    float acc = b_in[h];
    const float* w = W_in + h * HH;
#pragma unroll 8
    for (int d0 = 0; d0 < HH; d0 += 4) {
        float4 w4 = *(const float4*)(w + d0);
        acc += xs[d0] * w4.x + xs[d0+1] * w4.y + xs[d0+2] * w4.z + xs[d0+3] * w4.w;
    }
    g_inp[b * HH + h] = acc;
}

// ---------------------------------------------------------------------------
// Kernel 2: split W_ctx fp32 -> bf16 hi/lo
// ---------------------------------------------------------------------------
__global__ void k_wsplit(const float* __restrict__ W) {
    int i = blockIdx.x * 256 + threadIdx.x;
    float v = W[i];
    __nv_bfloat16 h = __float2bfloat16_rn(v);
    g_Bh[i] = h;
    g_Bl[i] = __float2bfloat16_rn(v - __bfloat162float(h));
}

// ---------------------------------------------------------------------------
// Kernel 3: split-bf16 HMMA GEMM + fused tanh-dot epilogue.  (R7 champion,
// with ONE change: MMA product index hoisted outermost so no two consecutive
// MMAs share an accumulator — 16 independent accs between same-c reuse.)
// CTA: M=64 rows, N=256, K=256 in 8 tiles of 32, double-buffered.
// 8 warps: wm = wid&1 (32 rows), wn = wid>>1 (64 cols).
// acc = Ah*Bh + Ah*Bl + Al*Bh   (lo*lo dropped ~2^-18)
// ---------------------------------------------------------------------------
#define MT 64
#define KT 32
#define PITCH 80
// smem byte offsets
#define OFF_A   0         // A[s]: + s*10240; hi at +0, lo at +5120
#define OFF_B   20480     // B[s][mat]: + s*2*20480 + mat*20480
#define OFF_IB  102400
#define OFF_V   103424
#define OFF_P   104448
#define SMEM_TOTAL 105472

__global__ __launch_bounds__(256, 2) void k_main(const float* __restrict__ context,
                                                 const float* __restrict__ b_ctx,
                                                 const float* __restrict__ V) {
    extern __shared__ char smem[];
    uint32_t sb = smem_u32(smem);
    int tid = threadIdx.x;
    int wid = tid >> 5, lid = tid & 31;
    int wm = wid & 1, wn = wid >> 1;
    int b = blockIdx.y;
    int m0 = blockIdx.x * MT;

    float* ibs = (float*)(smem + OFF_IB);
    float* vvs = (float*)(smem + OFF_V);
    ibs[tid] = g_inp[b * HH + tid] + b_ctx[tid];
    vvs[tid] = V[tid];

    const float* ctx = context + ((long)b * SS + m0) * DD;

    int arow = tid >> 2, aseg = tid & 3;
    const float* aptr = ctx + arow * DD + aseg * 8;
    {
        int k0 = 0;
#pragma unroll
        for (int r = 0; r < 8; r++) {
            int idx = tid + 256 * r;
            int mat = idx >> 10, rem = idx & 1023;
            int row = rem >> 2, c = rem & 3;
            const __nv_bfloat16* src = (mat ? g_Bl : g_Bh) + row * DD + k0 + c * 8;
            uint32_t dst = sb + OFF_B + mat * 20480 + row * PITCH + c * 16;
            CP_ASYNC16(dst, src);
        }
        CP_COMMIT();
    }
    float4 a0 = *(const float4*)(aptr);
    float4 a1 = *(const float4*)(aptr + 4);

    float c[2][8][4];
#pragma unroll
    for (int mi = 0; mi < 2; mi++)
#pragma unroll
        for (int j = 0; j < 8; j++)
#pragma unroll
            for (int e = 0; e < 4; e++) c[mi][j][e] = 0.f;

    for (int kt = 0; kt < DD / KT; kt++) {
        int s = kt & 1;
        // ---- convert prefetched A (fp32 -> bf16 hi/lo) into stage s
        {
            float f[8] = {a0.x, a0.y, a0.z, a0.w, a1.x, a1.y, a1.z, a1.w};
            uint32_t hi[4], lo[4];
#pragma unroll
            for (int e = 0; e < 4; e++) {
                __nv_bfloat16 h0 = __float2bfloat16_rn(f[2*e]);
                __nv_bfloat16 h1 = __float2bfloat16_rn(f[2*e+1]);
                __nv_bfloat16 l0 = __float2bfloat16_rn(f[2*e]   - __bfloat162float(h0));
                __nv_bfloat16 l1 = __float2bfloat16_rn(f[2*e+1] - __bfloat162float(h1));
                hi[e] = (uint32_t)__bfloat16_as_ushort(h0) | ((uint32_t)__bfloat16_as_ushort(h1) << 16);
                lo[e] = (uint32_t)__bfloat16_as_ushort(l0) | ((uint32_t)__bfloat16_as_ushort(l1) << 16);
            }
            char* base = smem + OFF_A + s * 10240 + arow * PITCH + aseg * 16;
            *(uint4*)(base)         = make_uint4(hi[0], hi[1], hi[2], hi[3]);
            *(uint4*)(base + 5120)  = make_uint4(lo[0], lo[1], lo[2], lo[3]);
        }
        CP_WAIT0();
        __syncthreads();

        // ---- prefetch next stage
        if (kt < DD / KT - 1) {
            int k0 = (kt + 1) * KT;
#pragma unroll
            for (int r = 0; r < 8; r++) {
                int idx = tid + 256 * r;
                int mat = idx >> 10, rem = idx & 1023;
                int row = rem >> 2, cc = rem & 3;
                const __nv_bfloat16* src = (mat ? g_Bl : g_Bh) + row * DD + k0 + cc * 8;
                uint32_t dst = sb + OFF_B + (s ^ 1) * 2 * 20480 + mat * 20480 + row * PITCH + cc * 16;
                CP_ASYNC16(dst, src);
            }
            CP_COMMIT();
            const float* ap = ctx + arow * DD + k0 + aseg * 8;
            a0 = *(const float4*)(ap);
            a1 = *(const float4*)(ap + 4);
        }

        // ---- MMAs over stage s
        uint32_t abase = sb + OFF_A + s * 10240;
        uint32_t bbase = sb + OFF_B + s * 2 * 20480;
#pragma unroll
        for (int ks = 0; ks < 2; ks++) {
            uint32_t aH[2][4], aL[2][4], bH[4][4], bL[4][4];
            int arow_f = wm * 32 + (lid & 15);
            int acol_b = ks * 32 + (lid >> 4) * 16;
#pragma unroll
            for (int mi = 0; mi < 2; mi++) {
                uint32_t ad = abase + (arow_f + mi * 16) * PITCH + acol_b;
                LDSM4(aH[mi][0], aH[mi][1], aH[mi][2], aH[mi][3], ad);
                LDSM4(aL[mi][0], aL[mi][1], aL[mi][2], aL[mi][3], ad + 5120);
            }
            int brow_f = wn * 64 + (lid & 7) + ((lid >> 4) * 8);
            int bcol_b = ks * 32 + ((lid >> 3) & 1) * 16;
#pragma unroll
            for (int jp = 0; jp < 4; jp++) {
                uint32_t bd = bbase + (brow_f + jp * 16) * PITCH + bcol_b;
                LDSM4(bH[jp][0], bH[jp][1], bH[jp][2], bH[jp][3], bd);
                LDSM4(bL[jp][0], bL[jp][1], bL[jp][2], bL[jp][3], bd + 20480);
            }
            // product loop OUTERMOST: consecutive MMAs never share an acc
#pragma unroll
            for (int p = 0; p < 3; p++)
#pragma unroll
                for (int mi = 0; mi < 2; mi++)
#pragma unroll
                    for (int j = 0; j < 8; j++) {
                        uint32_t b0, b1;
                        if (p == 1) { b0 = bL[j >> 1][(j & 1) * 2]; b1 = bL[j >> 1][(j & 1) * 2 + 1]; }
                        else        { b0 = bH[j >> 1][(j & 1) * 2]; b1 = bH[j >> 1][(j & 1) * 2 + 1]; }
                        if (p == 2) { MMA_BF16(c[mi][j], aL[mi], b0, b1); }
                        else        { MMA_BF16(c[mi][j], aH[mi], b0, b1); }
                    }
        }
    }

    // ---- epilogue: per-row tanh-dot with V
    {
        int q = lid & 3, g = lid >> 2;
        float ps[2][2] = {{0.f, 0.f}, {0.f, 0.f}};
#pragma unroll
        for (int mi = 0; mi < 2; mi++)
#pragma unroll
            for (int j = 0; j < 8; j++) {
                int h0 = wn * 64 + j * 8 + q * 2;
                ps[mi][0] += vvs[h0]   * tanhf(c[mi][j][0] + ibs[h0]);
                ps[mi][0] += vvs[h0+1] * tanhf(c[mi][j][1] + ibs[h0+1]);
                ps[mi][1] += vvs[h0]   * tanhf(c[mi][j][2] + ibs[h0]);
                ps[mi][1] += vvs[h0+1] * tanhf(c[mi][j][3] + ibs[h0+1]);
            }
#pragma unroll
        for (int off = 1; off <= 2; off <<= 1) {
#pragma unroll
            for (int mi = 0; mi < 2; mi++) {
                ps[mi][0] += __shfl_xor_sync(0xffffffffu, ps[mi][0], off);
                ps[mi][1] += __shfl_xor_sync(0xffffffffu, ps[mi][1], off);
            }
        }
        float* part = (float*)(smem + OFF_P);
        __syncthreads();
        if (q == 0) {
#pragma unroll
            for (int mi = 0; mi < 2; mi++) {
                part[(wm * 32 + mi * 16 + g) * 4 + wn]     = ps[mi][0];
                part[(wm * 32 + mi * 16 + g + 8) * 4 + wn] = ps[mi][1];
            }
        }
        __syncthreads();
        if (tid < MT) {
            float ssum = part[tid * 4] + part[tid * 4 + 1] + part[tid * 4 + 2] + part[tid * 4 + 3];
            g_att[b * SS + m0 + tid] = 10.f * tanhf(ssum);
        }
    }
}

// ---------------------------------------------------------------------------
// Kernel 4: mask echo + single-pass masked argmax + p = exp(max)/sum(exp).
// ---------------------------------------------------------------------------
__global__ __launch_bounds__(1024) void k_reduce(const int* __restrict__ mask,
                                                 float* __restrict__ out) {
    int b = blockIdx.x, tid = threadIdx.x;
    __shared__ float smax[1024], ssum[1024];
    __shared__ int   sidx[1024];

    float best = -INFINITY, se = 0.f;
    int bidx = 0x7fffffff;
    for (int s = tid; s < SS; s += 1024) {
        int m = mask[b * SS + s];
        out[2 * BB + b * SS + s] = m ? 1.f : 0.f;
        if (m) {
            float v = g_att[b * SS + s];
            se += expf(v);
            if (v > best || (v == best && s < bidx)) { best = v; bidx = s; }
        }
    }
    smax[tid] = best; sidx[tid] = bidx; ssum[tid] = se;
    __syncthreads();
    for (int off = 512; off; off >>= 1) {
        if (tid < off) {
            float v = smax[tid + off]; int ix = sidx[tid + off];
            if (v > smax[tid] || (v == smax[tid] && ix < sidx[tid])) {
                smax[tid] = v; sidx[tid] = ix;
            }
            ssum[tid] += ssum[tid + off];
        }
        __syncthreads();
    }
    if (tid == 0) {
        float rowmax = smax[0];
        out[b]      = (float)((rowmax == -INFINITY) ? 0 : sidx[0]);
        out[BB + b] = expf(rowmax) / ssum[0];
    }
}

// ---------------------------------------------------------------------------
extern "C" void kernel_launch(void* const* d_in, const int* in_sizes, int n_in,
                              void* d_out, int out_size) {
    const float* x      = (const float*)d_in[0];
    const float* contex = (const float*)d_in[1];
    const int*   mask   = (const int*)  d_in[2];
    const float* W_in   = (const float*)d_in[3];
    const float* b_in   = (const float*)d_in[4];
    const float* W_ctx  = (const float*)d_in[5];
    const float* b_ctx  = (const float*)d_in[6];
    const float* V      = (const float*)d_in[7];
    float* out = (float*)d_out;

    cudaFuncSetAttribute(k_main, cudaFuncAttributeMaxDynamicSharedMemorySize, SMEM_TOTAL);

    k_inp<<<BB, HH>>>(x, W_in, b_in);
    k_wsplit<<<HH * DD / 256, 256>>>(W_ctx);
    k_main<<<dim3(SS / MT, BB), 256, SMEM_TOTAL>>>(contex, b_ctx, V);
    k_reduce<<<BB, 1024>>>(mask, out);
}